// round 16
// baseline (speedup 1.0000x reference)
#include <cuda_runtime.h>
#include <cuda_bf16.h>
#include <cstdint>

typedef unsigned long long ull;

#define M_MODELS 3
#define B_IMG    16
#define N_BOX    512
#define K_TOT    (M_MODELS * N_BOX)   // 1536
#define NUM_CLS  12
#define CAPX     384                  // bucket capacity (mean 128, sigma ~11)
#define CAP      256                  // bitmask fast-path capacity
#define W_MAX    4                    // CAP/64
#define THR      512
#define GRID     (B_IMG * NUM_CLS)    // 192 independent blocks
#define CHUNK    384                  // K_TOT/4, global-rank scan chunk

__device__ __forceinline__ bool iou_gt(const float4 bi, const float ai,
                                       const float4 bj, const float aj) {
    // division-free exact IoU>0.5 test: 0.5*d is exact in fp32
    const float iw = fmaxf(fminf(bi.z, bj.z) - fmaxf(bi.x, bj.x), 0.0f);
    const float ih = fmaxf(fminf(bi.w, bj.w) - fmaxf(bi.y, bj.y), 0.0f);
    const float inter = iw * ih;
    const float uni   = ai + aj - inter;
    return inter > 0.5f * fmaxf(uni, 1e-9f);
}

// =============================================================================
// ONE kernel, 192 fully independent blocks = (image, class).
//   1. compute ALL 1536 keys of the image into smem; ballot-extract this
//      class's members
//   2. rank-count sort the bucket (keys distinct)
//   3. gather boxes (sentinel-padded), 16-warp bitmask build
//   4. tid0: sparse greedy chase  ||  tids>0: global-rank count
//      (rank = #keys strictly less, over all 1536 -> output row, no global sort)
//   5. write this bucket's output rows
// =============================================================================
__global__ __launch_bounds__(THR)
void k_nms_all(const float* __restrict__ boxes, const float* __restrict__ scores,
               const int* __restrict__ labels, const float* __restrict__ weights,
               float* __restrict__ out) {
    __shared__ ull           allkey[K_TOT];      // 12288 B
    __shared__ ull           skey[CAPX];         // 3072 B (extraction order)
    __shared__ ull           rkey[CAPX];         // 3072 B (rank order)
    __shared__ float4        bx[CAPX];           // 6144 B
    __shared__ float         ar[CAPX];           // 1536 B
    __shared__ ull           smask[CAP * W_MAX]; // 8192 B
    __shared__ ull           rownz[W_MAX];
    __shared__ ull           keepw[W_MAX];
    __shared__ int           grank[CAPX];        // 1536 B
    __shared__ unsigned char keepf[CAPX];        // fallback keep flags
    __shared__ int           s_cnt;

    const int img  = blockIdx.x / NUM_CLS;
    const int cls  = blockIdx.x % NUM_CLS;
    const int tid  = threadIdx.x;
    const int warp = tid >> 5, lane = tid & 31;

    const float w0 = weights[0], w1 = weights[1], w2 = weights[2];

    if (tid == 0) s_cnt = 0;
    if (tid < W_MAX) { rownz[tid] = 0ull; keepw[tid] = ~0ull; }
    __syncthreads();

    // ---- phase 1: all keys + ballot extraction of this class ----
    for (int e = tid; e < K_TOT; e += THR) {
        const int m = e >> 9, n = e & (N_BOX - 1);
        const size_t src = ((size_t)m * B_IMG + img) * N_BOX + n;
        const float wm = (m == 0) ? w0 : ((m == 1) ? w1 : w2);
        const float sc = scores[src] * wm;
        const ull kk = ((ull)(~__float_as_uint(sc)) << 32) | (unsigned)e;
        allkey[e] = kk;
        const bool p = (labels[src] == cls);
        const unsigned bal = __ballot_sync(0xffffffffu, p);
        int base = 0;
        if (lane == 0 && bal) base = atomicAdd(&s_cnt, __popc(bal));
        base = __shfl_sync(0xffffffffu, base, 0);
        if (p) {
            const int pos = base + __popc(bal & ((1u << lane) - 1u));
            if (pos < CAPX) skey[pos] = kk;
        }
    }
    __syncthreads();
    const int cnt = min(s_cnt, CAPX);
    if (cnt == 0) return;   // other blocks cover all other output rows

    // ---- phase 2: rank-count sort of the bucket (keys distinct) ----
    for (int m = tid; m < cnt; m += THR) {
        const ull k = skey[m];
        int r = 0;
        for (int j = 0; j < cnt; j++) r += (skey[j] < k);
        rkey[r] = k;
    }
    __syncthreads();

    // ---- phase 3: gather boxes in rank order (+ sentinels), init grank ----
    const int W    = (cnt + 63) >> 6;
    const int cpad = (cnt <= CAP) ? (W << 6) : cnt;
    for (int m = tid; m < cpad; m += THR) {
        if (m < cnt) {
            const int e = (int)(rkey[m] & 0xffffffffu);
            const int mm = e >> 9, nn = e & (N_BOX - 1);
            const float4 bb =
                *(const float4*)&boxes[(((size_t)mm * B_IMG + img) * N_BOX + nn) * 4];
            bx[m] = bb;
            ar[m] = (bb.z - bb.x) * (bb.w - bb.y);
            grank[m] = m;     // within-bucket rank contribution comes free below
        } else {
            bx[m] = make_float4(3e8f, 3e8f, 3e8f, 3e8f);  // never suppresses
            ar[m] = 0.0f;
        }
    }
    __syncthreads();

    if (cnt <= CAP) {
        // ---- branch-free bitmask build: rows striped over 16 warps ----
        for (int r = warp; r < cnt; r += 16) {
            const float4 bi = bx[r];
            const float  ai = ar[r];
            const int    wlo = r >> 6;
            ull nz = 0ull;
            for (int w = wlo; w < W; w++) {
                const int j0 = (w << 6) + lane;
                const bool p0 = iou_gt(bi, ai, bx[j0],      ar[j0]);
                const bool p1 = iou_gt(bi, ai, bx[j0 + 32], ar[j0 + 32]);
                ull mword = ((ull)__ballot_sync(0xffffffffu, p1) << 32)
                          |        __ballot_sync(0xffffffffu, p0);
                if (w == wlo)
                    mword &= ~((2ull << (r & 63)) - 1ull);   // clear j<=r
                if (lane == 0) smask[r * W_MAX + w] = mword;
                nz |= mword;
            }
            if (lane == 0 && nz)
                atomicOr(&rownz[r >> 6], 1ull << (r & 63));
        }
    }
    __syncthreads();

    // ---- phase 4: tid0 chase  ||  tids 1.. global-rank count ----
    if (tid == 0) {
        if (cnt <= CAP) {
            ull rem0 = 0, rem1 = 0, rem2 = 0, rem3 = 0;
            #pragma unroll
            for (int w = 0; w < W_MAX; w++) {
                if (w >= W) break;
                ull act = rownz[w];
                ull rw  = (w == 0) ? rem0 : (w == 1) ? rem1 : (w == 2) ? rem2 : rem3;
                act &= ~rw;
                while (act) {
                    const int bit = __ffsll((long long)act) - 1;
                    act &= act - 1;
                    if (!((rw >> bit) & 1ull)) {
                        const int i = (w << 6) + bit;
                        const ull* row = &smask[i * W_MAX];
                        if (w <= 0)          rem0 |= row[0];
                        if (w <= 1 && W > 1) rem1 |= row[1];
                        if (w <= 2 && W > 2) rem2 |= row[2];
                        if (w <= 3 && W > 3) rem3 |= row[3];
                        rw = (w == 0) ? rem0 : (w == 1) ? rem1 : (w == 2) ? rem2 : rem3;
                        act &= ~rw;
                    }
                }
            }
            keepw[0] = ~rem0; keepw[1] = ~rem1; keepw[2] = ~rem2; keepw[3] = ~rem3;
        }
    } else {
        // global-rank count: tasks = (element, chunk of 384 keys)
        // rank(m) = m (own bucket, already in grank) is WRONG in general —
        // we count over ALL keys below, so grank starts at m and we must NOT
        // double count own-bucket smaller keys. Trick: counting over allkey
        // includes own bucket, and own-bucket smaller count == m exactly.
        // So start from 0: subtract the preset m by atomicSub once per elem.
        // Simpler: chunk 0 task also does atomicSub(grank[m], m).
        for (int x = tid - 1; x < cnt * 4; x += THR - 1) {
            const int m  = x >> 2;
            const int c  = x & 3;
            const ull k  = rkey[m];
            const int j0 = c * CHUNK;
            int cp = 0;
            #pragma unroll 8
            for (int j = 0; j < CHUNK; j++)
                cp += (allkey[j0 + j] < k);
            if (c == 0) cp -= m;      // cancel the preset m (own-bucket dup)
            atomicAdd(&grank[m], cp);
        }
    }

    // ---- fallback chase (cnt > CAP, statistically impossible but correct) ----
    if (warp == 8 && cnt > CAP) {
        short* klist = (short*)smask;
        int nk = 0;
        for (int c = 0; c < cnt; c++) {
            const float4 bc = bx[c];
            const float  ac = ar[c];
            bool sup = false;
            for (int k = lane; k < nk; k += 32) {
                const int rr = klist[k];
                if (iou_gt(bc, ac, bx[rr], ar[rr])) { sup = true; break; }
            }
            sup = (__ballot_sync(0xffffffffu, sup) != 0u);
            if (!sup) {
                if (lane == 0) klist[nk] = (short)c;
                nk++;
            }
            if (lane == 0) keepf[c] = (unsigned char)(sup ? 0 : 1);
            __syncwarp();
        }
    }
    __syncthreads();

    // ---- phase 5: output this bucket's rows at their global ranks ----
    for (int m = tid; m < cnt; m += THR) {
        const bool kp = (cnt <= CAP)
                        ? (((keepw[m >> 6] >> (m & 63)) & 1ull) != 0ull)
                        : (keepf[m] != 0);
        const float f = kp ? 1.0f : 0.0f;
        const float4 bb = bx[m];
        const float  sc = __uint_as_float(~(unsigned)(rkey[m] >> 32));
        const size_t o  = ((size_t)img * K_TOT + grank[m]) * 5;
        out[o + 0] = bb.x * f;
        out[o + 1] = bb.y * f;
        out[o + 2] = bb.z * f;
        out[o + 3] = bb.w * f;
        out[o + 4] = sc * f;
    }
}

// =============================================================================
extern "C" void kernel_launch(void* const* d_in, const int* in_sizes, int n_in,
                              void* d_out, int out_size) {
    const float* boxes   = (const float*)d_in[0];
    const float* scores  = (const float*)d_in[1];
    const int*   labels  = (const int*)  d_in[2];
    const float* weights = (const float*)d_in[3];
    float*       out     = (float*)d_out;

    k_nms_all<<<GRID, THR>>>(boxes, scores, labels, weights, out);
}

// round 17
// speedup vs baseline: 1.7901x; 1.7901x over previous
#include <cuda_runtime.h>
#include <cuda_bf16.h>
#include <cstdint>

typedef unsigned long long ull;

#define M_MODELS 3
#define B_IMG    16
#define N_BOX    512
#define K_TOT    (M_MODELS * N_BOX)   // 1536
#define NUM_CLS  12
#define CAPX     384                  // bucket capacity (mean 128, +24 sigma)
#define CAP      256                  // bitmask fast-path capacity
#define W_MAX    4                    // CAP/64
#define THR      512
#define GRID     (B_IMG * NUM_CLS)    // 192 independent blocks

// ---------------- device scratch ----------------
__device__ ull           g_bkey [B_IMG][NUM_CLS][CAPX];  // sorted bucket keys
__device__ unsigned char g_bkeep[B_IMG][NUM_CLS][CAPX];  // keep by bucket pos
__device__ int           g_bcnt [B_IMG][NUM_CLS];
__device__ int           g_done [B_IMG];

__device__ __forceinline__ bool iou_gt(const float4 bi, const float ai,
                                       const float4 bj, const float aj) {
    // division-free exact IoU>0.5 test: 0.5*d is exact in fp32
    const float iw = fmaxf(fminf(bi.z, bj.z) - fmaxf(bi.x, bj.x), 0.0f);
    const float ih = fmaxf(fminf(bi.w, bj.w) - fmaxf(bi.y, bj.y), 0.0f);
    const float inter = iw * ih;
    const float uni   = ai + aj - inter;
    return inter > 0.5f * fmaxf(uni, 1e-9f);
}

struct NmsSh {                               // ~22.5 KB
    ull    skey[CAPX];
    ull    rkey[CAPX];
    float4 bx[CAPX];
    float  ar[CAPX];
    ull    smask[CAP * W_MAX];
    ull    rownz[W_MAX];
    ull    keepw[W_MAX];
    unsigned char keepf[CAPX];
};
struct EpiSh {                               // ~41.6 KB
    ull           keys[NUM_CLS][CAPX];
    unsigned char kp[NUM_CLS][CAPX];
    int           cnts[NUM_CLS];
    int           offs[NUM_CLS];
};
union ShU { NmsSh n; EpiSh e; };

// =============================================================================
// ONE kernel, 192 independent blocks = (image, class). No global sort.
// Per block: extract class keys -> rank-count sort -> matrix + chase ->
// publish (sorted keys, keep flags, count) -> arrival. The 12th arrival per
// image computes global ranks via 11 binary searches per element (12-way
// merge) and writes the output rows.
// =============================================================================
__global__ __launch_bounds__(THR)
void k_nms_all(const float* __restrict__ boxes, const float* __restrict__ scores,
               const int* __restrict__ labels, const float* __restrict__ weights,
               float* __restrict__ out) {
    __shared__ ShU sh;
    __shared__ int s_cnt, s_last;

    const int img  = blockIdx.x / NUM_CLS;
    const int cls  = blockIdx.x % NUM_CLS;
    const int tid  = threadIdx.x;
    const int warp = tid >> 5, lane = tid & 31;

    const float w0 = weights[0], w1 = weights[1], w2 = weights[2];

    if (tid == 0) s_cnt = 0;
    if (tid < W_MAX) { sh.n.rownz[tid] = 0ull; sh.n.keepw[tid] = ~0ull; }
    __syncthreads();

    // ---- phase 1: ballot-extract this class's keys ----
    for (int e = tid; e < K_TOT; e += THR) {
        const int m = e >> 9, n = e & (N_BOX - 1);
        const size_t src = ((size_t)m * B_IMG + img) * N_BOX + n;
        const bool p = (labels[src] == cls);
        ull kk = 0;
        if (p) {
            const float wm = (m == 0) ? w0 : ((m == 1) ? w1 : w2);
            const float sc = scores[src] * wm;
            kk = ((ull)(~__float_as_uint(sc)) << 32) | (unsigned)e;
        }
        const unsigned bal = __ballot_sync(0xffffffffu, p);
        int base = 0;
        if (lane == 0 && bal) base = atomicAdd(&s_cnt, __popc(bal));
        base = __shfl_sync(0xffffffffu, base, 0);
        if (p) {
            const int pos = base + __popc(bal & ((1u << lane) - 1u));
            if (pos < CAPX) sh.n.skey[pos] = kk;
        }
    }
    __syncthreads();
    const int cnt = min(s_cnt, CAPX);

    if (cnt > 0) {
        // ---- phase 2: rank-count sort (keys distinct) ----
        for (int m = tid; m < cnt; m += THR) {
            const ull k = sh.n.skey[m];
            int r = 0;
            for (int j = 0; j < cnt; j++) r += (sh.n.skey[j] < k);
            sh.n.rkey[r] = k;
        }
        __syncthreads();

        // ---- phase 3: gather boxes in rank order (+ sentinels) ----
        const int W    = (cnt + 63) >> 6;
        const int cpad = (cnt <= CAP) ? (W << 6) : cnt;
        for (int m = tid; m < cpad; m += THR) {
            if (m < cnt) {
                const int e = (int)(sh.n.rkey[m] & 0xffffffffu);
                const int mm = e >> 9, nn = e & (N_BOX - 1);
                const float4 bb =
                    *(const float4*)&boxes[(((size_t)mm * B_IMG + img) * N_BOX + nn) * 4];
                sh.n.bx[m] = bb;
                sh.n.ar[m] = (bb.z - bb.x) * (bb.w - bb.y);
            } else {
                sh.n.bx[m] = make_float4(3e8f, 3e8f, 3e8f, 3e8f);  // never suppresses
                sh.n.ar[m] = 0.0f;
            }
        }
        __syncthreads();

        if (cnt <= CAP) {
            // ---- branch-free bitmask build: rows striped over 16 warps ----
            for (int r = warp; r < cnt; r += 16) {
                const float4 bi = sh.n.bx[r];
                const float  ai = sh.n.ar[r];
                const int    wlo = r >> 6;
                ull nz = 0ull;
                for (int w = wlo; w < W; w++) {
                    const int j0 = (w << 6) + lane;
                    const bool p0 = iou_gt(bi, ai, sh.n.bx[j0],      sh.n.ar[j0]);
                    const bool p1 = iou_gt(bi, ai, sh.n.bx[j0 + 32], sh.n.ar[j0 + 32]);
                    ull mword = ((ull)__ballot_sync(0xffffffffu, p1) << 32)
                              |        __ballot_sync(0xffffffffu, p0);
                    if (w == wlo)
                        mword &= ~((2ull << (r & 63)) - 1ull);   // clear j<=r
                    if (lane == 0) sh.n.smask[r * W_MAX + w] = mword;
                    nz |= mword;
                }
                if (lane == 0 && nz)
                    atomicOr(&sh.n.rownz[r >> 6], 1ull << (r & 63));
            }
            __syncthreads();

            // ---- sparse greedy chase, single thread, registers ----
            if (tid == 0) {
                ull rem0 = 0, rem1 = 0, rem2 = 0, rem3 = 0;
                #pragma unroll
                for (int w = 0; w < W_MAX; w++) {
                    if (w >= W) break;
                    ull act = sh.n.rownz[w];
                    ull rw  = (w == 0) ? rem0 : (w == 1) ? rem1 : (w == 2) ? rem2 : rem3;
                    act &= ~rw;
                    while (act) {
                        const int bit = __ffsll((long long)act) - 1;
                        act &= act - 1;
                        if (!((rw >> bit) & 1ull)) {
                            const int i = (w << 6) + bit;
                            const ull* row = &sh.n.smask[i * W_MAX];
                            if (w <= 0)          rem0 |= row[0];
                            if (w <= 1 && W > 1) rem1 |= row[1];
                            if (w <= 2 && W > 2) rem2 |= row[2];
                            if (w <= 3 && W > 3) rem3 |= row[3];
                            rw = (w == 0) ? rem0 : (w == 1) ? rem1 : (w == 2) ? rem2 : rem3;
                            act &= ~rw;
                        }
                    }
                }
                sh.n.keepw[0] = ~rem0; sh.n.keepw[1] = ~rem1;
                sh.n.keepw[2] = ~rem2; sh.n.keepw[3] = ~rem3;
            }
        } else {
            // ---- fallback chase (cnt > CAP, pathological) ----
            if (warp == 0) {
                short* klist = (short*)sh.n.smask;
                int nk = 0;
                for (int c = 0; c < cnt; c++) {
                    const float4 bc = sh.n.bx[c];
                    const float  ac = sh.n.ar[c];
                    bool sup = false;
                    for (int k = lane; k < nk; k += 32) {
                        const int rr = klist[k];
                        if (iou_gt(bc, ac, sh.n.bx[rr], sh.n.ar[rr])) { sup = true; break; }
                    }
                    sup = (__ballot_sync(0xffffffffu, sup) != 0u);
                    if (!sup) {
                        if (lane == 0) klist[nk] = (short)c;
                        nk++;
                    }
                    if (lane == 0) sh.n.keepf[c] = (unsigned char)(sup ? 0 : 1);
                    __syncwarp();
                }
            }
        }
        __syncthreads();

        // ---- publish sorted keys + keep flags ----
        for (int m = tid; m < cnt; m += THR) {
            g_bkey[img][cls][m] = sh.n.rkey[m];
            g_bkeep[img][cls][m] = (cnt <= CAP)
                ? (unsigned char)((sh.n.keepw[m >> 6] >> (m & 63)) & 1ull)
                : sh.n.keepf[m];
        }
    }
    if (tid == 0) g_bcnt[img][cls] = cnt;

    // ---- arrival; 12th block per image runs the merge epilogue ----
    __threadfence();
    __syncthreads();
    if (tid == 0) {
        const int old = atomicAdd(&g_done[img], 1);
        s_last = (old == NUM_CLS - 1);
        if (s_last) __threadfence();
    }
    __syncthreads();
    if (!s_last) return;

    // =================== EPILOGUE (smem re-purposed) ===================
    __syncthreads();   // everyone past NMS-phase smem use
    if (tid < NUM_CLS) sh.e.cnts[tid] = g_bcnt[img][tid];
    __syncthreads();
    if (tid == 0) {
        int acc = 0;
        #pragma unroll
        for (int l = 0; l < NUM_CLS; l++) { sh.e.offs[l] = acc; acc += sh.e.cnts[l]; }
    }
    __syncthreads();

    // load all buckets' keys + keep flags
    for (int l = 0; l < NUM_CLS; l++) {
        const int c = sh.e.cnts[l];
        for (int m = tid; m < c; m += THR) {
            sh.e.keys[l][m] = g_bkey[img][l][m];
            sh.e.kp[l][m]   = g_bkeep[img][l][m];
        }
    }
    __syncthreads();

    // for each element: global rank = own pos + sum of lower_bounds in others
    for (int x = tid; x < K_TOT; x += THR) {
        // locate (bucket b, pos p)
        int b = 0;
        #pragma unroll
        for (int l = 1; l < NUM_CLS; l++) b += (x >= sh.e.offs[l]);
        const int p = x - sh.e.offs[b];
        if (p >= sh.e.cnts[b]) continue;      // only if truncation occurred
        const ull k = sh.e.keys[b][p];

        int rank = p;
        #pragma unroll
        for (int l = 0; l < NUM_CLS; l++) {
            if (l == b) continue;
            // lower_bound: count of keys < k in sorted keys[l]
            int lo = 0, hi = sh.e.cnts[l];
            while (lo < hi) {
                const int mid = (lo + hi) >> 1;
                if (sh.e.keys[l][mid] < k) lo = mid + 1; else hi = mid;
            }
            rank += lo;
        }

        const int e = (int)(k & 0xffffffffu);
        const int mm = e >> 9, nn = e & (N_BOX - 1);
        const float4 bb =
            *(const float4*)&boxes[(((size_t)mm * B_IMG + img) * N_BOX + nn) * 4];
        const float sc = __uint_as_float(~(unsigned)(k >> 32));
        const float f  = sh.e.kp[b][p] ? 1.0f : 0.0f;
        const size_t o = ((size_t)img * K_TOT + rank) * 5;
        out[o + 0] = bb.x * f;
        out[o + 1] = bb.y * f;
        out[o + 2] = bb.z * f;
        out[o + 3] = bb.w * f;
        out[o + 4] = sc * f;
    }
    __syncthreads();
    if (tid == 0) g_done[img] = 0;   // reset for next graph replay
}

// =============================================================================
extern "C" void kernel_launch(void* const* d_in, const int* in_sizes, int n_in,
                              void* d_out, int out_size) {
    const float* boxes   = (const float*)d_in[0];
    const float* scores  = (const float*)d_in[1];
    const int*   labels  = (const int*)  d_in[2];
    const float* weights = (const float*)d_in[3];
    float*       out     = (float*)d_out;

    k_nms_all<<<GRID, THR>>>(boxes, scores, labels, weights, out);
}